// round 12
// baseline (speedup 1.0000x reference)
#include <cuda_runtime.h>
#include <cuda_fp16.h>
#include <cstdint>

// ============================================================================
// BlockG via mma.sync fp16 single-term implicit GEMM, fully cp.async-pipelined.
//   conv = scale-input-by-style, shared-weight conv, scale-output-by-demod.
//   3x3 conv = 9 row-offset taps into a double-buffered padded-NHWC smem region;
//   next chunk's X prefetched in 8 slices riding the per-tap weight groups.
// Output: d_out[0:8*512*64*64) = x (fp32 NCHW), then [..:+8*3*64*64) = rgb.
// ============================================================================

#define B_ 8
#define C_ 512
#define PIX 4096
#define XEL (B_*C_*PIX)
#define QW 66
#define SLAB 4496
#define NT 256
#define NTILES 17
#define REGROWS 392            // 8 * 49
#define EPSV 1e-8f
#define SLOPE 0.2f

// dynamic smem layout (bytes; all 1024-aligned)
#define OFF_X0 0
#define OFF_X1 50176
#define OFF_W  100352
#define WBUF   16384
#define SMEM_CONV 133120

// ---------------- device scratch ----------------
__device__ __half g_x1[B_*SLAB*C_];                 // conv1 input (padded NHWC fp16)
__device__ __half g_x2[B_*SLAB*C_];                 // conv2 input
__device__ __half g_wb1[9*C_*C_], g_wb2[9*C_*C_];   // [tap][co][ci] fp16
__device__ float g_w2s1[C_*C_], g_w2s2[C_*C_];
__device__ float g_s1[B_*C_], g_s2[B_*C_], g_s3[B_*C_];
__device__ float g_d1[B_*C_], g_d2[B_*C_];
__device__ float g_m3[B_*3*C_];

// ---------------- helpers ----------------
__device__ __forceinline__ uint32_t smem_u32(const void* p) {
    uint32_t a;
    asm("{ .reg .u64 t; cvta.to.shared.u64 t, %1; cvt.u32.u64 %0, t; }" : "=r"(a) : "l"(p));
    return a;
}
__device__ __forceinline__ uint32_t swz(uint32_t o) { return o ^ ((o >> 3) & 0x70); }

__device__ __forceinline__ void cpa16(uint32_t dst, const void* gsrc) {
    asm volatile("cp.async.cg.shared.global [%0], [%1], 16;"
        :: "r"(dst), "l"(__cvta_generic_to_global(gsrc)) : "memory");
}
__device__ __forceinline__ void cpa_commit() {
    asm volatile("cp.async.commit_group;" ::: "memory");
}
__device__ __forceinline__ void cpa_wait0() {
    asm volatile("cp.async.wait_group 0;" ::: "memory");
}

__device__ __forceinline__ void ldsm4(uint32_t* r, uint32_t addr) {
    asm volatile("ldmatrix.sync.aligned.m8n8.x4.shared.b16 {%0,%1,%2,%3}, [%4];"
        : "=r"(r[0]), "=r"(r[1]), "=r"(r[2]), "=r"(r[3]) : "r"(addr));
}
__device__ __forceinline__ void mma16816(float* c, const uint32_t* a, uint32_t b0, uint32_t b1) {
    asm volatile("mma.sync.aligned.m16n8k16.row.col.f32.f16.f16.f32 "
        "{%0,%1,%2,%3}, {%4,%5,%6,%7}, {%8,%9}, {%0,%1,%2,%3};"
        : "+f"(c[0]), "+f"(c[1]), "+f"(c[2]), "+f"(c[3])
        : "r"(a[0]), "r"(a[1]), "r"(a[2]), "r"(a[3]), "r"(b0), "r"(b1));
}

// ---------------- styles ----------------
__global__ void k_styles(const float* __restrict__ w,
                         const float* __restrict__ A1, const float* __restrict__ b1,
                         const float* __restrict__ A2, const float* __restrict__ b2,
                         const float* __restrict__ A3, const float* __restrict__ b3)
{
    int gw = (blockIdx.x * blockDim.x + threadIdx.x) >> 5;
    int lane = threadIdx.x & 31;
    if (gw >= 3 * B_ * C_) return;
    int m = gw / (B_ * C_);
    int r = gw - m * (B_ * C_);
    int b = r >> 9, i = r & 511;
    const float* A  = (m == 0) ? A1 : (m == 1) ? A2 : A3;
    const float* bs = (m == 0) ? b1 : (m == 1) ? b2 : b3;
    float acc = 0.f;
    const float* wb = w + b * C_;
    const float* Ai = A + i * C_;
    for (int k = lane; k < C_; k += 32) acc += wb[k] * Ai[k];
    #pragma unroll
    for (int o = 16; o > 0; o >>= 1) acc += __shfl_xor_sync(0xffffffffu, acc, o);
    if (lane == 0) {
        float* out = (m == 0) ? g_s1 : (m == 1) ? g_s2 : g_s3;
        out[b * C_ + i] = acc + bs[i];
    }
}

// ---------------- weight prep: sumsq + fp16 transpose -----------------------
__global__ void k_wprep(const float* __restrict__ w1, const float* __restrict__ w2)
{
    int idx = blockIdx.x * blockDim.x + threadIdx.x;
    if (idx >= 2 * C_ * C_) return;
    int m = idx >> 18;
    int r = idx & (C_ * C_ - 1);
    int co = r >> 9, ci = r & 511;
    const float* w = m ? w2 : w1;
    float* w2s = m ? g_w2s2 : g_w2s1;
    __half* wh = m ? g_wb2 : g_wb1;
    const float* src = w + (size_t)(co * C_ + ci) * 9;
    float ss = 0.f;
    #pragma unroll
    for (int t = 0; t < 9; t++) {
        float v = src[t];
        ss += v * v;
        wh[((size_t)t * C_ + co) * C_ + ci] = __float2half_rn(v);
    }
    w2s[co * C_ + ci] = ss;
}

// ---------------- demod ----------------
__global__ void k_demod()
{
    int gw = (blockIdx.x * blockDim.x + threadIdx.x) >> 5;
    int lane = threadIdx.x & 31;
    if (gw >= 2 * B_ * C_) return;
    int m = gw >> 12;
    int r = gw & 4095;
    int b = r >> 9, co = r & 511;
    const float* w2s = m ? g_w2s2 : g_w2s1;
    const float* s   = m ? g_s2   : g_s1;
    float acc = 0.f;
    const float* wr = w2s + co * C_;
    const float* sr = s + b * C_;
    for (int ci = lane; ci < C_; ci += 32) { float sv = sr[ci]; acc += wr[ci] * sv * sv; }
    #pragma unroll
    for (int o = 16; o > 0; o >>= 1) acc += __shfl_xor_sync(0xffffffffu, acc, o);
    if (lane == 0) {
        float* d = m ? g_d2 : g_d1;
        d[b * C_ + co] = rsqrtf(acc + EPSV);
    }
}

// ---------------- toRGB modulation ----------------
__global__ void k_m3(const float* __restrict__ w3)
{
    int b = blockIdx.x / 3, j = blockIdx.x % 3;
    __shared__ float red[128];
    __shared__ float d3s;
    int tid = threadIdx.x;
    float acc = 0.f;
    for (int ci = tid; ci < C_; ci += 128) {
        float t = w3[j * C_ + ci] * g_s3[b * C_ + ci];
        acc += t * t;
    }
    red[tid] = acc; __syncthreads();
    for (int o = 64; o > 0; o >>= 1) { if (tid < o) red[tid] += red[tid + o]; __syncthreads(); }
    if (tid == 0) d3s = rsqrtf(red[0] + EPSV);
    __syncthreads();
    float d3 = d3s;
    for (int ci = tid; ci < C_; ci += 128)
        g_m3[(b * 3 + j) * C_ + ci] = w3[j * C_ + ci] * g_s3[b * C_ + ci] * d3;
}

// ---------------- zero borders + tail of padded NHWC buffers ----------------
// rows to zero per batch: top 66, bottom 66, left 64, right 64, tail 140 = 400
__global__ void k_zero()
{
    int i = blockIdx.x % 400;
    int b = blockIdx.x / 400;
    int q;
    if (i < 66)       q = i;                          // top row (y'=0)
    else if (i < 132) q = 4290 + (i - 66);            // bottom row (y'=65)
    else if (i < 196) q = (i - 132 + 1) * QW;         // left col
    else if (i < 260) q = (i - 196 + 1) * QW + 65;    // right col
    else              q = 4356 + (i - 260);           // tail rows [4356,4496)
    size_t o = ((size_t)b * SLAB + q) * C_ / 2 + threadIdx.x;
    ((uint32_t*)g_x1)[o] = 0u;
    ((uint32_t*)g_x2)[o] = 0u;
}

// ---------------- upsample x2 + style, write fp16 NHWC ----------------------
__global__ void k_up(const float* __restrict__ xin)
{
    int y = blockIdx.x, cc = blockIdx.y, b = blockIdx.z;
    int ci0 = cc * 64;
    __shared__ float sin_[2][64][33];
    __shared__ float ss1[64];
    const float F = 31.0f / 63.0f;
    float cy = (float)y * F;
    int iy0 = (int)cy;
    float ty = cy - (float)iy0;
    int iy1 = min(iy0 + 1, 31);
    int tid = threadIdx.x;
    for (int i = tid; i < 2 * 64 * 32; i += 256) {
        int rr = i >> 11, rem = i & 2047, c = rem >> 5, xx = rem & 31;
        int iy = rr ? iy1 : iy0;
        sin_[rr][c][xx] = xin[((size_t)(b * C_ + ci0 + c) * 32 + iy) * 32 + xx];
    }
    if (tid < 64) ss1[tid] = g_s1[b * C_ + ci0 + tid];
    __syncthreads();
    #pragma unroll
    for (int j = 0; j < 16; j++) {
        int x = (tid >> 6) + j * 4;
        int c = tid & 63;
        float cx = (float)x * F;
        int ix0 = (int)cx;
        float tx = cx - (float)ix0;
        int ix1 = min(ix0 + 1, 31);
        float a0 = sin_[0][c][ix0] * (1.f - ty) + sin_[1][c][ix0] * ty;
        float a1 = sin_[0][c][ix1] * (1.f - ty) + sin_[1][c][ix1] * ty;
        float v = (a0 * (1.f - tx) + a1 * tx) * ss1[c];
        size_t o = ((size_t)b * SLAB + (y + 1) * QW + (x + 1)) * C_ + ci0 + c;
        g_x1[o] = __float2half_rn(v);
    }
}

// ---------------- mma.sync conv 3x3, fully pipelined ------------------------
// CTA: 128 co x 256 px, 8 warps (2m x 4n) each m64 x n64. Single fp16 term.
// X double-buffered; next chunk's X prefetched in 8 slices during taps 0..7.
__global__ void __launch_bounds__(256)
k_conv(int pass, const float* __restrict__ noise, const float* __restrict__ Bvec,
       float* __restrict__ outx)
{
    extern __shared__ __align__(1024) char dsm[];

    const __half* xin = pass ? g_x2  : g_x1;
    const __half* wb  = pass ? g_wb2 : g_wb1;
    const float* dm = pass ? g_d2 : g_d1;

    int tid = threadIdx.x;
    int wid = tid >> 5, lane = tid & 31;
    int wm = wid & 1, wn = wid >> 1;          // warp pos: m (co), n (px 0..3)
    int b = blockIdx.z, cb = blockIdx.y, ntile = blockIdx.x;
    int P0 = ntile * NT;
    int co_base = cb * 128;

    uint32_t sb = smem_u32(dsm);

    // ldmatrix lane geometry
    int a_row = ((lane >> 3) & 1) * 8 + (lane & 7);
    int a_kb  = (lane >> 4) * 16;
    int b_n   = (lane >> 4) * 8 + (lane & 7);
    int b_kb  = ((lane >> 3) & 1) * 16;

    float acc[4][8][4];
    #pragma unroll
    for (int mi = 0; mi < 4; mi++)
        #pragma unroll
        for (int f = 0; f < 8; f++)
            #pragma unroll
            for (int r = 0; r < 4; r++) acc[mi][f][r] = 0.f;

    uint32_t rowA[4];
    #pragma unroll
    for (int mi = 0; mi < 4; mi++)
        rowA[mi] = (uint32_t)((wm * 64 + mi * 16 + a_row) * 128 + a_kb);

    const size_t xgbase = ((size_t)b * SLAB + P0) * C_;

    // full X stage (prologue only)
    auto stage_X_full = [&](int c, uint32_t xoff) {
        int ci0 = c * 64;
        for (int i = tid; i < REGROWS * 8; i += 256) {
            int r = i >> 3, j = i & 7;
            size_t g = xgbase + (size_t)r * C_ + ci0 + j * 8;
            cpa16(sb + xoff + swz((uint32_t)(r * 128 + j * 16)), xin + g);
        }
    };
    // 1/8 of an X region: rows [slice*49, slice*49+49)
    auto stage_X_slice = [&](int c, int slice, uint32_t xoff) {
        int ci0 = c * 64;
        int r0 = slice * 49;
        for (int i = tid; i < 49 * 8; i += 256) {
            int r = r0 + (i >> 3), j = i & 7;
            size_t g = xgbase + (size_t)r * C_ + ci0 + j * 8;
            cpa16(sb + xoff + swz((uint32_t)(r * 128 + j * 16)), xin + g);
        }
    };
    auto stage_W = [&](int c, int tap, int buf) {
        int ci0 = c * 64;
        const size_t wgbase = ((size_t)(tap * C_ + co_base)) * C_ + ci0;
        uint32_t base = sb + OFF_W + buf * WBUF;
        for (int i = tid; i < 128 * 8; i += 256) {
            int r = i >> 3, j = i & 7;
            size_t g = wgbase + (size_t)r * C_ + j * 8;
            cpa16(base + swz((uint32_t)(r * 128 + j * 16)), wb + g);
        }
    };

    // prologue: chunk-0 X into buffer 0 + first weight tap
    stage_X_full(0, OFF_X0);
    stage_W(0, 0, 0);
    cpa_commit();
    cpa_wait0();
    __syncthreads();

    int wcur = 0, xcur = 0;
    for (int c = 0; c < 8; c++) {
        uint32_t sX = sb + (xcur ? OFF_X1 : OFF_X0);
        uint32_t sXn = sb + (xcur ? OFF_X0 : OFF_X1);
        for (int tap = 0; tap < 9; tap++) {
            bool last = (c == 7 && tap == 8);
            // prefetch: next weight tile (+ a slice of next chunk's X)
            if (!last) {
                if (tap < 8) {
                    stage_W(c, tap + 1, wcur ^ 1);
                    if (c < 7) stage_X_slice(c + 1, tap, sXn - sb);
                } else {
                    stage_W(c + 1, 0, wcur ^ 1);
                }
                cpa_commit();
            }

            // compute this tap from W[wcur] + X[xcur]
            uint32_t sW = sb + OFF_W + wcur * WBUF;
            int toff = (tap / 3) * QW + (tap % 3);
            uint32_t rowB[4];
            #pragma unroll
            for (int nj = 0; nj < 4; nj++)
                rowB[nj] = (uint32_t)((wn * 64 + nj * 16 + b_n + toff) * 128 + b_kb);

            #pragma unroll
            for (int ks = 0; ks < 4; ks++) {
                uint32_t kadd = ks * 32;
                uint32_t Aw[4][4], Bx[4][4];
                #pragma unroll
                for (int mi = 0; mi < 4; mi++)
                    ldsm4(Aw[mi], sW + swz(rowA[mi] + kadd));
                #pragma unroll
                for (int nj = 0; nj < 4; nj++)
                    ldsm4(Bx[nj], sX + swz(rowB[nj] + kadd));
                #pragma unroll
                for (int mi = 0; mi < 4; mi++) {
                    #pragma unroll
                    for (int f = 0; f < 8; f++) {
                        int bi = f >> 1, br = (f & 1) * 2;
                        mma16816(acc[mi][f], Aw[mi], Bx[bi][br], Bx[bi][br + 1]);
                    }
                }
            }

            if (!last) {
                cpa_wait0();
                __syncthreads();
            }
            wcur ^= 1;
        }
        xcur ^= 1;
    }

    // ---------------- epilogue ----------------
    int g = lane >> 2, c2 = (lane & 3) * 2;
    #pragma unroll
    for (int mi = 0; mi < 4; mi++) {
        #pragma unroll
        for (int rh = 0; rh < 2; rh++) {
            int co_g = co_base + wm * 64 + mi * 16 + g + rh * 8;
            float d   = dm[b * C_ + co_g];
            float bb  = Bvec[co_g];
            float s2v = pass ? 1.f : g_s2[b * C_ + co_g];
            #pragma unroll
            for (int f = 0; f < 8; f++) {
                #pragma unroll
                for (int rl = 0; rl < 2; rl++) {
                    int col = wn * 64 + f * 8 + c2 + rl;
                    int p = P0 + col;
                    int y = p / QW;
                    int x = p - y * QW;
                    if (x < 64 && y < 64) {
                        float v = d * acc[mi][f][rh * 2 + rl] + bb * noise[b * PIX + y * 64 + x];
                        v = (v >= 0.f) ? v : SLOPE * v;
                        if (pass == 0) {
                            v *= s2v;
                            size_t o = ((size_t)b * SLAB + (y + 1) * QW + (x + 1)) * C_ + co_g;
                            g_x2[o] = __float2half_rn(v);
                        } else {
                            outx[((size_t)(b * C_ + co_g)) * PIX + y * 64 + x] = v;
                        }
                    }
                }
            }
        }
    }
}

// ---------------- toRGB 1x1 + rgb upsample + add ----------------------------
__device__ __forceinline__ float bilerp32(const float* __restrict__ p, int y, int x)
{
    const float F = 31.0f / 63.0f;
    float cy = (float)y * F, cx = (float)x * F;
    int iy0 = (int)cy, ix0 = (int)cx;
    float ty = cy - (float)iy0, tx = cx - (float)ix0;
    int iy1 = min(iy0 + 1, 31), ix1 = min(ix0 + 1, 31);
    float v00 = p[iy0 * 32 + ix0], v01 = p[iy0 * 32 + ix1];
    float v10 = p[iy1 * 32 + ix0], v11 = p[iy1 * 32 + ix1];
    float a = v00 * (1.f - ty) + v10 * ty;
    float c = v01 * (1.f - ty) + v11 * ty;
    return a * (1.f - tx) + c * tx;
}

__global__ void k_final(const float* __restrict__ y2,
                        const float* __restrict__ rgb_in,
                        const float* __restrict__ noise3,
                        const float* __restrict__ B3,
                        float* __restrict__ out_rgb)
{
    int b = blockIdx.y;
    int p = blockIdx.x * 256 + threadIdx.x;
    __shared__ float s_m3[3 * C_];
    for (int i = threadIdx.x; i < 3 * C_; i += 256) s_m3[i] = g_m3[b * 3 * C_ + i];
    __syncthreads();

    int y = p >> 6, x = p & 63;
    const float* yb = y2 + (size_t)b * C_ * PIX + p;
    float a0 = 0.f, a1 = 0.f, a2 = 0.f;
    #pragma unroll 8
    for (int ci = 0; ci < C_; ci++) {
        float v = yb[(size_t)ci * PIX];
        a0 = fmaf(s_m3[ci], v, a0);
        a1 = fmaf(s_m3[C_ + ci], v, a1);
        a2 = fmaf(s_m3[2 * C_ + ci], v, a2);
    }
    float nz = noise3[b * PIX + p];
    float a[3] = {a0, a1, a2};
    #pragma unroll
    for (int j = 0; j < 3; j++) {
        float v = a[j] + B3[j] * nz;
        v = (v >= 0.f) ? v : SLOPE * v;
        const float* rp = rgb_in + (size_t)(b * 3 + j) * 1024;
        out_rgb[(size_t)(b * 3 + j) * PIX + p] = bilerp32(rp, y, x) + v;
    }
}

// ---------------- launcher ---------------------------------------------------
extern "C" void kernel_launch(void* const* d_in, const int* in_sizes, int n_in,
                              void* d_out, int out_size)
{
    const float* x    = (const float*)d_in[0];
    const float* rgb  = (const float*)d_in[1];
    const float* w    = (const float*)d_in[2];
    const float* n1   = (const float*)d_in[3];
    const float* n2   = (const float*)d_in[4];
    const float* n3   = (const float*)d_in[5];
    const float* wt1  = (const float*)d_in[6];
    const float* A1w  = (const float*)d_in[7];
    const float* A1b  = (const float*)d_in[8];
    const float* B1   = (const float*)d_in[9];
    const float* wt2  = (const float*)d_in[10];
    const float* A2w  = (const float*)d_in[11];
    const float* A2b  = (const float*)d_in[12];
    const float* B2   = (const float*)d_in[13];
    const float* wt3  = (const float*)d_in[14];
    const float* A3w  = (const float*)d_in[15];
    const float* A3b  = (const float*)d_in[16];
    const float* B3   = (const float*)d_in[17];
    float* out = (float*)d_out;

    cudaFuncSetAttribute(k_conv, cudaFuncAttributeMaxDynamicSharedMemorySize, SMEM_CONV);

    k_styles<<<(3 * B_ * C_ + 7) / 8, 256>>>(w, A1w, A1b, A2w, A2b, A3w, A3b);
    k_wprep <<<(2 * C_ * C_ + 255) / 256, 256>>>(wt1, wt2);
    k_demod <<<(2 * B_ * C_ + 7) / 8, 256>>>();
    k_m3    <<<B_ * 3, 128>>>(wt3);
    k_zero  <<<B_ * 400, 256>>>();
    k_up    <<<dim3(64, 8, B_), 256>>>(x);
    k_conv  <<<dim3(NTILES, 4, B_), 256, SMEM_CONV>>>(0, n1, B1, out);
    k_conv  <<<dim3(NTILES, 4, B_), 256, SMEM_CONV>>>(1, n2, B2, out);
    k_final <<<dim3(PIX / 256, B_), 256>>>(out, rgb, n3, B3, out + (size_t)XEL);
}

// round 14
// speedup vs baseline: 1.0390x; 1.0390x over previous
#include <cuda_runtime.h>
#include <cuda_fp16.h>
#include <cstdint>

// ============================================================================
// BlockG via mma.sync fp16 single-term implicit GEMM.
//   conv = scale-input-by-style, shared-weight conv, scale-output-by-demod.
//   3x3 conv = 9 row-offset taps into one padded-NHWC smem region.
//   Depth-2 weight pipeline (3 buffers, wait_group 1): never block on the
//   just-issued transfer. Conv1 epilogue staged through smem for coalescing.
// Output: d_out[0:8*512*64*64) = x (fp32 NCHW), then [..:+8*3*64*64) = rgb.
// ============================================================================

#define B_ 8
#define C_ 512
#define PIX 4096
#define XEL (B_*C_*PIX)
#define QW 66
#define SLAB 4496
#define NT 256
#define NTILES 17
#define REGROWS 392
#define NIT 72                 // 8 chunks * 9 taps
#define EPSV 1e-8f
#define SLOPE 0.2f

// dynamic smem layout (bytes)
#define OFF_X  0
#define OFF_W  50176
#define WBUF   16384
#define SMEM_CONV 99328        // 50176 + 3*16384

// ---------------- device scratch ----------------
__device__ __half g_x1[B_*SLAB*C_];                 // conv1 input (padded NHWC fp16)
__device__ __half g_x2[B_*SLAB*C_];                 // conv2 input
__device__ __half g_wb1[9*C_*C_], g_wb2[9*C_*C_];   // [tap][co][ci] fp16
__device__ float g_w2s1[C_*C_], g_w2s2[C_*C_];
__device__ float g_s1[B_*C_], g_s2[B_*C_], g_s3[B_*C_];
__device__ float g_d1[B_*C_], g_d2[B_*C_];
__device__ float g_m3[B_*3*C_];

// ---------------- helpers ----------------
__device__ __forceinline__ uint32_t smem_u32(const void* p) {
    uint32_t a;
    asm("{ .reg .u64 t; cvta.to.shared.u64 t, %1; cvt.u32.u64 %0, t; }" : "=r"(a) : "l"(p));
    return a;
}
__device__ __forceinline__ uint32_t swz(uint32_t o) { return o ^ ((o >> 3) & 0x70); }

__device__ __forceinline__ void cpa16(uint32_t dst, const void* gsrc) {
    asm volatile("cp.async.cg.shared.global [%0], [%1], 16;"
        :: "r"(dst), "l"(__cvta_generic_to_global(gsrc)) : "memory");
}
__device__ __forceinline__ void cpa_commit() {
    asm volatile("cp.async.commit_group;" ::: "memory");
}
__device__ __forceinline__ void cpa_wait0() {
    asm volatile("cp.async.wait_group 0;" ::: "memory");
}
__device__ __forceinline__ void cpa_wait1() {
    asm volatile("cp.async.wait_group 1;" ::: "memory");
}

__device__ __forceinline__ void ldsm4(uint32_t* r, uint32_t addr) {
    asm volatile("ldmatrix.sync.aligned.m8n8.x4.shared.b16 {%0,%1,%2,%3}, [%4];"
        : "=r"(r[0]), "=r"(r[1]), "=r"(r[2]), "=r"(r[3]) : "r"(addr));
}
__device__ __forceinline__ void mma16816(float* c, const uint32_t* a, uint32_t b0, uint32_t b1) {
    asm volatile("mma.sync.aligned.m16n8k16.row.col.f32.f16.f16.f32 "
        "{%0,%1,%2,%3}, {%4,%5,%6,%7}, {%8,%9}, {%0,%1,%2,%3};"
        : "+f"(c[0]), "+f"(c[1]), "+f"(c[2]), "+f"(c[3])
        : "r"(a[0]), "r"(a[1]), "r"(a[2]), "r"(a[3]), "r"(b0), "r"(b1));
}

// ---------------- styles ----------------
__global__ void k_styles(const float* __restrict__ w,
                         const float* __restrict__ A1, const float* __restrict__ b1,
                         const float* __restrict__ A2, const float* __restrict__ b2,
                         const float* __restrict__ A3, const float* __restrict__ b3)
{
    int gw = (blockIdx.x * blockDim.x + threadIdx.x) >> 5;
    int lane = threadIdx.x & 31;
    if (gw >= 3 * B_ * C_) return;
    int m = gw / (B_ * C_);
    int r = gw - m * (B_ * C_);
    int b = r >> 9, i = r & 511;
    const float* A  = (m == 0) ? A1 : (m == 1) ? A2 : A3;
    const float* bs = (m == 0) ? b1 : (m == 1) ? b2 : b3;
    float acc = 0.f;
    const float* wb = w + b * C_;
    const float* Ai = A + i * C_;
    for (int k = lane; k < C_; k += 32) acc += wb[k] * Ai[k];
    #pragma unroll
    for (int o = 16; o > 0; o >>= 1) acc += __shfl_xor_sync(0xffffffffu, acc, o);
    if (lane == 0) {
        float* out = (m == 0) ? g_s1 : (m == 1) ? g_s2 : g_s3;
        out[b * C_ + i] = acc + bs[i];
    }
}

// ---------------- weight prep: sumsq + fp16 transpose -----------------------
__global__ void k_wprep(const float* __restrict__ w1, const float* __restrict__ w2)
{
    int idx = blockIdx.x * blockDim.x + threadIdx.x;
    if (idx >= 2 * C_ * C_) return;
    int m = idx >> 18;
    int r = idx & (C_ * C_ - 1);
    int co = r >> 9, ci = r & 511;
    const float* w = m ? w2 : w1;
    float* w2s = m ? g_w2s2 : g_w2s1;
    __half* wh = m ? g_wb2 : g_wb1;
    const float* src = w + (size_t)(co * C_ + ci) * 9;
    float ss = 0.f;
    #pragma unroll
    for (int t = 0; t < 9; t++) {
        float v = src[t];
        ss += v * v;
        wh[((size_t)t * C_ + co) * C_ + ci] = __float2half_rn(v);
    }
    w2s[co * C_ + ci] = ss;
}

// ---------------- demod ----------------
__global__ void k_demod()
{
    int gw = (blockIdx.x * blockDim.x + threadIdx.x) >> 5;
    int lane = threadIdx.x & 31;
    if (gw >= 2 * B_ * C_) return;
    int m = gw >> 12;
    int r = gw & 4095;
    int b = r >> 9, co = r & 511;
    const float* w2s = m ? g_w2s2 : g_w2s1;
    const float* s   = m ? g_s2   : g_s1;
    float acc = 0.f;
    const float* wr = w2s + co * C_;
    const float* sr = s + b * C_;
    for (int ci = lane; ci < C_; ci += 32) { float sv = sr[ci]; acc += wr[ci] * sv * sv; }
    #pragma unroll
    for (int o = 16; o > 0; o >>= 1) acc += __shfl_xor_sync(0xffffffffu, acc, o);
    if (lane == 0) {
        float* d = m ? g_d2 : g_d1;
        d[b * C_ + co] = rsqrtf(acc + EPSV);
    }
}

// ---------------- toRGB modulation ----------------
__global__ void k_m3(const float* __restrict__ w3)
{
    int b = blockIdx.x / 3, j = blockIdx.x % 3;
    __shared__ float red[128];
    __shared__ float d3s;
    int tid = threadIdx.x;
    float acc = 0.f;
    for (int ci = tid; ci < C_; ci += 128) {
        float t = w3[j * C_ + ci] * g_s3[b * C_ + ci];
        acc += t * t;
    }
    red[tid] = acc; __syncthreads();
    for (int o = 64; o > 0; o >>= 1) { if (tid < o) red[tid] += red[tid + o]; __syncthreads(); }
    if (tid == 0) d3s = rsqrtf(red[0] + EPSV);
    __syncthreads();
    float d3 = d3s;
    for (int ci = tid; ci < C_; ci += 128)
        g_m3[(b * 3 + j) * C_ + ci] = w3[j * C_ + ci] * g_s3[b * C_ + ci] * d3;
}

// ---------------- zero borders + tail of padded NHWC buffers ----------------
__global__ void k_zero()
{
    int i = blockIdx.x % 400;
    int b = blockIdx.x / 400;
    int q;
    if (i < 66)       q = i;                          // top row
    else if (i < 132) q = 4290 + (i - 66);            // bottom row
    else if (i < 196) q = (i - 132 + 1) * QW;         // left col
    else if (i < 260) q = (i - 196 + 1) * QW + 65;    // right col
    else              q = 4356 + (i - 260);           // tail rows [4356,4496)
    size_t o = ((size_t)b * SLAB + q) * C_ / 2 + threadIdx.x;
    ((uint32_t*)g_x1)[o] = 0u;
    ((uint32_t*)g_x2)[o] = 0u;
}

// ---------------- upsample x2 + style, write fp16 NHWC ----------------------
__global__ void k_up(const float* __restrict__ xin)
{
    int y = blockIdx.x, cc = blockIdx.y, b = blockIdx.z;
    int ci0 = cc * 64;
    __shared__ float sin_[2][64][33];
    __shared__ float ss1[64];
    const float F = 31.0f / 63.0f;
    float cy = (float)y * F;
    int iy0 = (int)cy;
    float ty = cy - (float)iy0;
    int iy1 = min(iy0 + 1, 31);
    int tid = threadIdx.x;
    for (int i = tid; i < 2 * 64 * 32; i += 256) {
        int rr = i >> 11, rem = i & 2047, c = rem >> 5, xx = rem & 31;
        int iy = rr ? iy1 : iy0;
        sin_[rr][c][xx] = xin[((size_t)(b * C_ + ci0 + c) * 32 + iy) * 32 + xx];
    }
    if (tid < 64) ss1[tid] = g_s1[b * C_ + ci0 + tid];
    __syncthreads();
    #pragma unroll
    for (int j = 0; j < 16; j++) {
        int x = (tid >> 6) + j * 4;
        int c = tid & 63;
        float cx = (float)x * F;
        int ix0 = (int)cx;
        float tx = cx - (float)ix0;
        int ix1 = min(ix0 + 1, 31);
        float a0 = sin_[0][c][ix0] * (1.f - ty) + sin_[1][c][ix0] * ty;
        float a1 = sin_[0][c][ix1] * (1.f - ty) + sin_[1][c][ix1] * ty;
        float v = (a0 * (1.f - tx) + a1 * tx) * ss1[c];
        size_t o = ((size_t)b * SLAB + (y + 1) * QW + (x + 1)) * C_ + ci0 + c;
        g_x1[o] = __float2half_rn(v);
    }
}

// ---------------- mma.sync conv 3x3, depth-2 weight pipeline ----------------
// CTA: 128 co x 256 px, 8 warps (2m x 4n) each m64 x n64. Single fp16 term.
__global__ void __launch_bounds__(256)
k_conv(int pass, const float* __restrict__ noise, const float* __restrict__ Bvec,
       float* __restrict__ outx)
{
    extern __shared__ __align__(1024) char dsm[];

    const __half* xin = pass ? g_x2  : g_x1;
    const __half* wb  = pass ? g_wb2 : g_wb1;
    const float* dm = pass ? g_d2 : g_d1;

    int tid = threadIdx.x;
    int wid = tid >> 5, lane = tid & 31;
    int wm = wid & 1, wn = wid >> 1;          // warp pos: m (co), n (px 0..3)
    int b = blockIdx.z, cb = blockIdx.y, ntile = blockIdx.x;
    int P0 = ntile * NT;
    int co_base = cb * 128;

    uint32_t sb = smem_u32(dsm);
    uint32_t sX = sb + OFF_X;

    // ldmatrix lane geometry
    int a_row = ((lane >> 3) & 1) * 8 + (lane & 7);
    int a_kb  = (lane >> 4) * 16;
    int b_n   = (lane >> 4) * 8 + (lane & 7);
    int b_kb  = ((lane >> 3) & 1) * 16;

    float acc[4][8][4];
    #pragma unroll
    for (int mi = 0; mi < 4; mi++)
        #pragma unroll
        for (int f = 0; f < 8; f++)
            #pragma unroll
            for (int r = 0; r < 4; r++) acc[mi][f][r] = 0.f;

    uint32_t rowA[4];
    #pragma unroll
    for (int mi = 0; mi < 4; mi++)
        rowA[mi] = (uint32_t)((wm * 64 + mi * 16 + a_row) * 128 + a_kb);

    const size_t xgbase = ((size_t)b * SLAB + P0) * C_;

    auto stage_X = [&](int c) {
        int ci0 = c * 64;
        for (int i = tid; i < REGROWS * 8; i += 256) {
            int r = i >> 3, j = i & 7;
            size_t g = xgbase + (size_t)r * C_ + ci0 + j * 8;
            cpa16(sX + swz((uint32_t)(r * 128 + j * 16)), xin + g);
        }
    };
    // weight tile for global iteration k (chunk k/9, tap k%9) into buffer k%3
    auto stage_Wk = [&](int k) {
        int c = k / 9, tap = k - c * 9;
        int ci0 = c * 64;
        const size_t wgbase = ((size_t)(tap * C_ + co_base)) * C_ + ci0;
        uint32_t base = sb + OFF_W + (uint32_t)(k % 3) * WBUF;
        for (int i = tid; i < 128 * 8; i += 256) {
            int r = i >> 3, j = i & 7;
            size_t g = wgbase + (size_t)r * C_ + j * 8;
            cpa16(base + swz((uint32_t)(r * 128 + j * 16)), wb + g);
        }
    };

    // prologue: X(0)+W(0) as group0, W(1) as group1; drain group0; publish.
    stage_X(0);
    stage_Wk(0);
    cpa_commit();
    stage_Wk(1);
    cpa_commit();
    cpa_wait1();                // X + W(0) landed
    __syncthreads();

    for (int it = 0; it < NIT; it++) {
        int c = it / 9, tap = it - c * 9;
        bool xmove = (tap == 0 && c > 0);

        if (it > 0) __syncthreads();   // readers of W buf[(it+2)%3] and X done
        if (xmove) stage_X(c);
        if (it + 2 < NIT) stage_Wk(it + 2);
        cpa_commit();                  // one group per iteration (may be small)
        if (xmove) {
            cpa_wait0();               // X needed immediately
            __syncthreads();           // publish X to all warps
        } else {
            cpa_wait1();               // drain W(it+1); W(it) landed at it-1
        }

        // compute tap from W buf[it%3] + resident X
        uint32_t sW = sb + OFF_W + (uint32_t)(it % 3) * WBUF;
        int toff = (tap / 3) * QW + (tap % 3);
        uint32_t rowB[4];
        #pragma unroll
        for (int nj = 0; nj < 4; nj++)
            rowB[nj] = (uint32_t)((wn * 64 + nj * 16 + b_n + toff) * 128 + b_kb);

        #pragma unroll
        for (int ks = 0; ks < 4; ks++) {
            uint32_t kadd = ks * 32;
            uint32_t Aw[4][4], Bx[4][4];
            #pragma unroll
            for (int mi = 0; mi < 4; mi++)
                ldsm4(Aw[mi], sW + swz(rowA[mi] + kadd));
            #pragma unroll
            for (int nj = 0; nj < 4; nj++)
                ldsm4(Bx[nj], sX + swz(rowB[nj] + kadd));
            #pragma unroll
            for (int mi = 0; mi < 4; mi++) {
                #pragma unroll
                for (int f = 0; f < 8; f++) {
                    int bi = f >> 1, br = (f & 1) * 2;
                    mma16816(acc[mi][f], Aw[mi], Bx[bi][br], Bx[bi][br + 1]);
                }
            }
        }
    }

    // ---------------- epilogue ----------------
    int g = lane >> 2, c2 = (lane & 3) * 2;
    if (pass == 0) {
        // stage [col][co] fp16 in smem (row stride 272B), then coalesced store
        __syncthreads();               // mainloop smem reads done
        const int RS = 272;
        #pragma unroll
        for (int mi = 0; mi < 4; mi++) {
            #pragma unroll
            for (int rh = 0; rh < 2; rh++) {
                int co_t = wm * 64 + mi * 16 + g + rh * 8;
                int co_g = co_base + co_t;
                float d   = dm[b * C_ + co_g];
                float bb  = Bvec[co_g];
                float s2v = g_s2[b * C_ + co_g];
                #pragma unroll
                for (int f = 0; f < 8; f++) {
                    #pragma unroll
                    for (int rl = 0; rl < 2; rl++) {
                        int col = wn * 64 + f * 8 + c2 + rl;
                        int p = P0 + col;
                        int y = p / QW;
                        int x = p - y * QW;
                        float v = 0.f;
                        if (x < 64 && y < 64) {
                            v = d * acc[mi][f][rh * 2 + rl] + bb * noise[b * PIX + y * 64 + x];
                            v = (v >= 0.f) ? v : SLOPE * v;
                            v *= s2v;
                        }
                        *(__half*)(dsm + col * RS + co_t * 2) = __float2half_rn(v);
                    }
                }
            }
        }
        __syncthreads();
        for (int i = tid; i < 256 * 16; i += 256) {
            int px = i >> 4, j = i & 15;
            int p = P0 + px;
            int y = p / QW;
            int x = p - y * QW;
            if (x < 64 && y < 64) {
                uint4 val = *(const uint4*)(dsm + px * RS + j * 16);
                char* dst = (char*)(g_x2 + ((size_t)b * SLAB + (y + 1) * QW + (x + 1)) * C_ + co_base);
                *(uint4*)(dst + j * 16) = val;
            }
        }
    } else {
        #pragma unroll
        for (int mi = 0; mi < 4; mi++) {
            #pragma unroll
            for (int rh = 0; rh < 2; rh++) {
                int co_g = co_base + wm * 64 + mi * 16 + g + rh * 8;
                float d  = dm[b * C_ + co_g];
                float bb = Bvec[co_g];
                #pragma unroll
                for (int f = 0; f < 8; f++) {
                    #pragma unroll
                    for (int rl = 0; rl < 2; rl++) {
                        int col = wn * 64 + f * 8 + c2 + rl;
                        int p = P0 + col;
                        int y = p / QW;
                        int x = p - y * QW;
                        if (x < 64 && y < 64) {
                            float v = d * acc[mi][f][rh * 2 + rl] + bb * noise[b * PIX + y * 64 + x];
                            v = (v >= 0.f) ? v : SLOPE * v;
                            outx[((size_t)(b * C_ + co_g)) * PIX + y * 64 + x] = v;
                        }
                    }
                }
            }
        }
    }
}

// ---------------- toRGB 1x1 + rgb upsample + add ----------------------------
__device__ __forceinline__ float bilerp32(const float* __restrict__ p, int y, int x)
{
    const float F = 31.0f / 63.0f;
    float cy = (float)y * F, cx = (float)x * F;
    int iy0 = (int)cy, ix0 = (int)cx;
    float ty = cy - (float)iy0, tx = cx - (float)ix0;
    int iy1 = min(iy0 + 1, 31), ix1 = min(ix0 + 1, 31);
    float v00 = p[iy0 * 32 + ix0], v01 = p[iy0 * 32 + ix1];
    float v10 = p[iy1 * 32 + ix0], v11 = p[iy1 * 32 + ix1];
    float a = v00 * (1.f - ty) + v10 * ty;
    float c = v01 * (1.f - ty) + v11 * ty;
    return a * (1.f - tx) + c * tx;
}

__global__ void k_final(const float* __restrict__ y2,
                        const float* __restrict__ rgb_in,
                        const float* __restrict__ noise3,
                        const float* __restrict__ B3,
                        float* __restrict__ out_rgb)
{
    int b = blockIdx.y;
    int p = blockIdx.x * 256 + threadIdx.x;
    __shared__ float s_m3[3 * C_];
    for (int i = threadIdx.x; i < 3 * C_; i += 256) s_m3[i] = g_m3[b * 3 * C_ + i];
    __syncthreads();

    int y = p >> 6, x = p & 63;
    const float* yb = y2 + (size_t)b * C_ * PIX + p;
    float a0 = 0.f, a1 = 0.f, a2 = 0.f;
    #pragma unroll 8
    for (int ci = 0; ci < C_; ci++) {
        float v = yb[(size_t)ci * PIX];
        a0 = fmaf(s_m3[ci], v, a0);
        a1 = fmaf(s_m3[C_ + ci], v, a1);
        a2 = fmaf(s_m3[2 * C_ + ci], v, a2);
    }
    float nz = noise3[b * PIX + p];
    float a[3] = {a0, a1, a2};
    #pragma unroll
    for (int j = 0; j < 3; j++) {
        float v = a[j] + B3[j] * nz;
        v = (v >= 0.f) ? v : SLOPE * v;
        const float* rp = rgb_in + (size_t)(b * 3 + j) * 1024;
        out_rgb[(size_t)(b * 3 + j) * PIX + p] = bilerp32(rp, y, x) + v;
    }
}

// ---------------- launcher ---------------------------------------------------
extern "C" void kernel_launch(void* const* d_in, const int* in_sizes, int n_in,
                              void* d_out, int out_size)
{
    const float* x    = (const float*)d_in[0];
    const float* rgb  = (const float*)d_in[1];
    const float* w    = (const float*)d_in[2];
    const float* n1   = (const float*)d_in[3];
    const float* n2   = (const float*)d_in[4];
    const float* n3   = (const float*)d_in[5];
    const float* wt1  = (const float*)d_in[6];
    const float* A1w  = (const float*)d_in[7];
    const float* A1b  = (const float*)d_in[8];
    const float* B1   = (const float*)d_in[9];
    const float* wt2  = (const float*)d_in[10];
    const float* A2w  = (const float*)d_in[11];
    const float* A2b  = (const float*)d_in[12];
    const float* B2   = (const float*)d_in[13];
    const float* wt3  = (const float*)d_in[14];
    const float* A3w  = (const float*)d_in[15];
    const float* A3b  = (const float*)d_in[16];
    const float* B3   = (const float*)d_in[17];
    float* out = (float*)d_out;

    cudaFuncSetAttribute(k_conv, cudaFuncAttributeMaxDynamicSharedMemorySize, SMEM_CONV);

    k_styles<<<(3 * B_ * C_ + 7) / 8, 256>>>(w, A1w, A1b, A2w, A2b, A3w, A3b);
    k_wprep <<<(2 * C_ * C_ + 255) / 256, 256>>>(wt1, wt2);
    k_demod <<<(2 * B_ * C_ + 7) / 8, 256>>>();
    k_m3    <<<B_ * 3, 128>>>(wt3);
    k_zero  <<<B_ * 400, 256>>>();
    k_up    <<<dim3(64, 8, B_), 256>>>(x);
    k_conv  <<<dim3(NTILES, 4, B_), 256, SMEM_CONV>>>(0, n1, B1, out);
    k_conv  <<<dim3(NTILES, 4, B_), 256, SMEM_CONV>>>(1, n2, B2, out);
    k_final <<<dim3(PIX / 256, B_), 256>>>(out, rgb, n3, B3, out + (size_t)XEL);
}

// round 15
// speedup vs baseline: 1.0463x; 1.0071x over previous
#include <cuda_runtime.h>
#include <cuda_fp16.h>
#include <cstdint>

// ============================================================================
// BlockG via mma.sync fp16 single-term implicit GEMM.
//   conv = scale-input-by-style, shared-weight conv, scale-output-by-demod.
//   3x3 conv = 9 row-offset taps into one padded-NHWC smem region.
//   Depth-2 weight pipeline (3 buffers, wait_group 1).
//   192-px n-tiles: 4224 = 22*192 exactly -> no junk tile, 704 CTAs (95% util).
// Output: d_out[0:8*512*64*64) = x (fp32 NCHW), then [..:+8*3*64*64) = rgb.
// ============================================================================

#define B_ 8
#define C_ 512
#define PIX 4096
#define XEL (B_*C_*PIX)
#define QW 66
#define SLAB 4496
#define NT 192
#define NTILES 22
#define REGROWS 326
#define NIT 72                 // 8 chunks * 9 taps
#define EPSV 1e-8f
#define SLOPE 0.2f

// dynamic smem layout (bytes)
#define OFF_X  0
#define OFF_W  41728           // 326*128
#define WBUF   16384
#define SMEM_CONV 90880        // 41728 + 3*16384

// ---------------- device scratch ----------------
__device__ __half g_x1[B_*SLAB*C_];                 // conv1 input (padded NHWC fp16)
__device__ __half g_x2[B_*SLAB*C_];                 // conv2 input
__device__ __half g_wb1[9*C_*C_], g_wb2[9*C_*C_];   // [tap][co][ci] fp16
__device__ float g_w2s1[C_*C_], g_w2s2[C_*C_];
__device__ float g_s1[B_*C_], g_s2[B_*C_], g_s3[B_*C_];
__device__ float g_d1[B_*C_], g_d2[B_*C_];
__device__ float g_m3[B_*3*C_];

// ---------------- helpers ----------------
__device__ __forceinline__ uint32_t smem_u32(const void* p) {
    uint32_t a;
    asm("{ .reg .u64 t; cvta.to.shared.u64 t, %1; cvt.u32.u64 %0, t; }" : "=r"(a) : "l"(p));
    return a;
}
__device__ __forceinline__ uint32_t swz(uint32_t o) { return o ^ ((o >> 3) & 0x70); }

__device__ __forceinline__ void cpa16(uint32_t dst, const void* gsrc) {
    asm volatile("cp.async.cg.shared.global [%0], [%1], 16;"
        :: "r"(dst), "l"(__cvta_generic_to_global(gsrc)) : "memory");
}
__device__ __forceinline__ void cpa_commit() {
    asm volatile("cp.async.commit_group;" ::: "memory");
}
__device__ __forceinline__ void cpa_wait0() {
    asm volatile("cp.async.wait_group 0;" ::: "memory");
}
__device__ __forceinline__ void cpa_wait1() {
    asm volatile("cp.async.wait_group 1;" ::: "memory");
}

__device__ __forceinline__ void ldsm4(uint32_t* r, uint32_t addr) {
    asm volatile("ldmatrix.sync.aligned.m8n8.x4.shared.b16 {%0,%1,%2,%3}, [%4];"
        : "=r"(r[0]), "=r"(r[1]), "=r"(r[2]), "=r"(r[3]) : "r"(addr));
}
__device__ __forceinline__ void mma16816(float* c, const uint32_t* a, uint32_t b0, uint32_t b1) {
    asm volatile("mma.sync.aligned.m16n8k16.row.col.f32.f16.f16.f32 "
        "{%0,%1,%2,%3}, {%4,%5,%6,%7}, {%8,%9}, {%0,%1,%2,%3};"
        : "+f"(c[0]), "+f"(c[1]), "+f"(c[2]), "+f"(c[3])
        : "r"(a[0]), "r"(a[1]), "r"(a[2]), "r"(a[3]), "r"(b0), "r"(b1));
}

// ---------------- styles + weight prep (merged, independent work) -----------
// blocks [0, 1536): styles (8 warps each); blocks [1536, 3584): wprep
__global__ void k_prep(const float* __restrict__ w,
                       const float* __restrict__ A1, const float* __restrict__ b1,
                       const float* __restrict__ A2, const float* __restrict__ b2,
                       const float* __restrict__ A3, const float* __restrict__ b3,
                       const float* __restrict__ w1, const float* __restrict__ w2)
{
    if (blockIdx.x < 1536) {
        int gw = (blockIdx.x * 256 + threadIdx.x) >> 5;
        int lane = threadIdx.x & 31;
        int m = gw / (B_ * C_);
        int r = gw - m * (B_ * C_);
        int b = r >> 9, i = r & 511;
        const float* A  = (m == 0) ? A1 : (m == 1) ? A2 : A3;
        const float* bs = (m == 0) ? b1 : (m == 1) ? b2 : b3;
        float acc = 0.f;
        const float* wb = w + b * C_;
        const float* Ai = A + i * C_;
        for (int k = lane; k < C_; k += 32) acc += wb[k] * Ai[k];
        #pragma unroll
        for (int o = 16; o > 0; o >>= 1) acc += __shfl_xor_sync(0xffffffffu, acc, o);
        if (lane == 0) {
            float* out = (m == 0) ? g_s1 : (m == 1) ? g_s2 : g_s3;
            out[b * C_ + i] = acc + bs[i];
        }
    } else {
        int idx = (blockIdx.x - 1536) * 256 + threadIdx.x;
        int m = idx >> 18;
        int r = idx & (C_ * C_ - 1);
        int co = r >> 9, ci = r & 511;
        const float* wsrc = m ? w2 : w1;
        float* w2s = m ? g_w2s2 : g_w2s1;
        __half* wh = m ? g_wb2 : g_wb1;
        const float* src = wsrc + (size_t)(co * C_ + ci) * 9;
        float ss = 0.f;
        #pragma unroll
        for (int t = 0; t < 9; t++) {
            float v = src[t];
            ss += v * v;
            wh[((size_t)t * C_ + co) * C_ + ci] = __float2half_rn(v);
        }
        w2s[co * C_ + ci] = ss;
    }
}

// ---------------- demod ----------------
__global__ void k_demod()
{
    int gw = (blockIdx.x * blockDim.x + threadIdx.x) >> 5;
    int lane = threadIdx.x & 31;
    if (gw >= 2 * B_ * C_) return;
    int m = gw >> 12;
    int r = gw & 4095;
    int b = r >> 9, co = r & 511;
    const float* w2s = m ? g_w2s2 : g_w2s1;
    const float* s   = m ? g_s2   : g_s1;
    float acc = 0.f;
    const float* wr = w2s + co * C_;
    const float* sr = s + b * C_;
    for (int ci = lane; ci < C_; ci += 32) { float sv = sr[ci]; acc += wr[ci] * sv * sv; }
    #pragma unroll
    for (int o = 16; o > 0; o >>= 1) acc += __shfl_xor_sync(0xffffffffu, acc, o);
    if (lane == 0) {
        float* d = m ? g_d2 : g_d1;
        d[b * C_ + co] = rsqrtf(acc + EPSV);
    }
}

// ---------------- toRGB modulation ----------------
__global__ void k_m3(const float* __restrict__ w3)
{
    int b = blockIdx.x / 3, j = blockIdx.x % 3;
    __shared__ float red[128];
    __shared__ float d3s;
    int tid = threadIdx.x;
    float acc = 0.f;
    for (int ci = tid; ci < C_; ci += 128) {
        float t = w3[j * C_ + ci] * g_s3[b * C_ + ci];
        acc += t * t;
    }
    red[tid] = acc; __syncthreads();
    for (int o = 64; o > 0; o >>= 1) { if (tid < o) red[tid] += red[tid + o]; __syncthreads(); }
    if (tid == 0) d3s = rsqrtf(red[0] + EPSV);
    __syncthreads();
    float d3 = d3s;
    for (int ci = tid; ci < C_; ci += 128)
        g_m3[(b * 3 + j) * C_ + ci] = w3[j * C_ + ci] * g_s3[b * C_ + ci] * d3;
}

// ---------------- zero borders + tail of padded NHWC buffers ----------------
__global__ void k_zero()
{
    int i = blockIdx.x % 400;
    int b = blockIdx.x / 400;
    int q;
    if (i < 66)       q = i;                          // top row
    else if (i < 132) q = 4290 + (i - 66);            // bottom row
    else if (i < 196) q = (i - 132 + 1) * QW;         // left col
    else if (i < 260) q = (i - 196 + 1) * QW + 65;    // right col
    else              q = 4356 + (i - 260);           // tail rows [4356,4496)
    size_t o = ((size_t)b * SLAB + q) * C_ / 2 + threadIdx.x;
    ((uint32_t*)g_x1)[o] = 0u;
    ((uint32_t*)g_x2)[o] = 0u;
}

// ---------------- upsample x2 + style, write fp16 NHWC ----------------------
__global__ void k_up(const float* __restrict__ xin)
{
    int y = blockIdx.x, cc = blockIdx.y, b = blockIdx.z;
    int ci0 = cc * 64;
    __shared__ float sin_[2][64][33];
    __shared__ float ss1[64];
    const float F = 31.0f / 63.0f;
    float cy = (float)y * F;
    int iy0 = (int)cy;
    float ty = cy - (float)iy0;
    int iy1 = min(iy0 + 1, 31);
    int tid = threadIdx.x;
    for (int i = tid; i < 2 * 64 * 32; i += 256) {
        int rr = i >> 11, rem = i & 2047, c = rem >> 5, xx = rem & 31;
        int iy = rr ? iy1 : iy0;
        sin_[rr][c][xx] = xin[((size_t)(b * C_ + ci0 + c) * 32 + iy) * 32 + xx];
    }
    if (tid < 64) ss1[tid] = g_s1[b * C_ + ci0 + tid];
    __syncthreads();
    #pragma unroll
    for (int j = 0; j < 16; j++) {
        int x = (tid >> 6) + j * 4;
        int c = tid & 63;
        float cx = (float)x * F;
        int ix0 = (int)cx;
        float tx = cx - (float)ix0;
        int ix1 = min(ix0 + 1, 31);
        float a0 = sin_[0][c][ix0] * (1.f - ty) + sin_[1][c][ix0] * ty;
        float a1 = sin_[0][c][ix1] * (1.f - ty) + sin_[1][c][ix1] * ty;
        float v = (a0 * (1.f - tx) + a1 * tx) * ss1[c];
        size_t o = ((size_t)b * SLAB + (y + 1) * QW + (x + 1)) * C_ + ci0 + c;
        g_x1[o] = __float2half_rn(v);
    }
}

// ---------------- mma.sync conv 3x3, depth-2 weight pipeline ----------------
// CTA: 128 co x 192 px, 8 warps (2m x 4n) each m64 x n48. Single fp16 term.
__global__ void __launch_bounds__(256)
k_conv(int pass, const float* __restrict__ noise, const float* __restrict__ Bvec,
       float* __restrict__ outx)
{
    extern __shared__ __align__(1024) char dsm[];

    const __half* xin = pass ? g_x2  : g_x1;
    const __half* wb  = pass ? g_wb2 : g_wb1;
    const float* dm = pass ? g_d2 : g_d1;

    int tid = threadIdx.x;
    int wid = tid >> 5, lane = tid & 31;
    int wm = wid & 1, wn = wid >> 1;          // warp pos: m (co), n (px 0..3)
    int b = blockIdx.z, cb = blockIdx.y, ntile = blockIdx.x;
    int P0 = ntile * NT;
    int co_base = cb * 128;

    uint32_t sb = smem_u32(dsm);
    uint32_t sX = sb + OFF_X;

    // ldmatrix lane geometry
    int a_row = ((lane >> 3) & 1) * 8 + (lane & 7);
    int a_kb  = (lane >> 4) * 16;
    int b_n   = (lane >> 4) * 8 + (lane & 7);
    int b_kb  = ((lane >> 3) & 1) * 16;

    float acc[4][6][4];
    #pragma unroll
    for (int mi = 0; mi < 4; mi++)
        #pragma unroll
        for (int f = 0; f < 6; f++)
            #pragma unroll
            for (int r = 0; r < 4; r++) acc[mi][f][r] = 0.f;

    uint32_t rowA[4];
    #pragma unroll
    for (int mi = 0; mi < 4; mi++)
        rowA[mi] = (uint32_t)((wm * 64 + mi * 16 + a_row) * 128 + a_kb);

    const size_t xgbase = ((size_t)b * SLAB + P0) * C_;

    auto stage_X = [&](int c) {
        int ci0 = c * 64;
        for (int i = tid; i < REGROWS * 8; i += 256) {
            int r = i >> 3, j = i & 7;
            size_t g = xgbase + (size_t)r * C_ + ci0 + j * 8;
            cpa16(sX + swz((uint32_t)(r * 128 + j * 16)), xin + g);
        }
    };
    // weight tile for global iteration k (chunk k/9, tap k%9) into buffer k%3
    auto stage_Wk = [&](int k) {
        int c = k / 9, tap = k - c * 9;
        int ci0 = c * 64;
        const size_t wgbase = ((size_t)(tap * C_ + co_base)) * C_ + ci0;
        uint32_t base = sb + OFF_W + (uint32_t)(k % 3) * WBUF;
        for (int i = tid; i < 128 * 8; i += 256) {
            int r = i >> 3, j = i & 7;
            size_t g = wgbase + (size_t)r * C_ + j * 8;
            cpa16(base + swz((uint32_t)(r * 128 + j * 16)), wb + g);
        }
    };

    // prologue: X(0)+W(0) as group0, W(1) as group1; drain group0; publish.
    stage_X(0);
    stage_Wk(0);
    cpa_commit();
    stage_Wk(1);
    cpa_commit();
    cpa_wait1();                // X + W(0) landed
    __syncthreads();

    for (int it = 0; it < NIT; it++) {
        int c = it / 9, tap = it - c * 9;
        bool xmove = (tap == 0 && c > 0);

        if (it > 0) __syncthreads();   // readers of W buf[(it+2)%3] and X done
        if (xmove) stage_X(c);
        if (it + 2 < NIT) stage_Wk(it + 2);
        cpa_commit();                  // one group per iteration
        if (xmove) {
            cpa_wait0();               // X needed immediately
            __syncthreads();           // publish X to all warps
        } else {
            cpa_wait1();               // drain W(it+1); W(it) landed at it-1
        }

        // compute tap from W buf[it%3] + resident X
        uint32_t sW = sb + OFF_W + (uint32_t)(it % 3) * WBUF;
        int toff = (tap / 3) * QW + (tap % 3);
        uint32_t rowB[3];
        #pragma unroll
        for (int nj = 0; nj < 3; nj++)
            rowB[nj] = (uint32_t)((wn * 48 + nj * 16 + b_n + toff) * 128 + b_kb);

        #pragma unroll
        for (int ks = 0; ks < 4; ks++) {
            uint32_t kadd = ks * 32;
            uint32_t Aw[4][4], Bx[3][4];
            #pragma unroll
            for (int mi = 0; mi < 4; mi++)
                ldsm4(Aw[mi], sW + swz(rowA[mi] + kadd));
            #pragma unroll
            for (int nj = 0; nj < 3; nj++)
                ldsm4(Bx[nj], sX + swz(rowB[nj] + kadd));
            #pragma unroll
            for (int mi = 0; mi < 4; mi++) {
                #pragma unroll
                for (int f = 0; f < 6; f++) {
                    int bi = f >> 1, br = (f & 1) * 2;
                    mma16816(acc[mi][f], Aw[mi], Bx[bi][br], Bx[bi][br + 1]);
                }
            }
        }
    }

    // ---------------- epilogue ----------------
    int g = lane >> 2, c2 = (lane & 3) * 2;
    if (pass == 0) {
        // stage [col][co] fp16 in smem (row stride 272B), then coalesced store
        __syncthreads();               // mainloop smem reads done
        const int RS = 272;
        #pragma unroll
        for (int mi = 0; mi < 4; mi++) {
            #pragma unroll
            for (int rh = 0; rh < 2; rh++) {
                int co_t = wm * 64 + mi * 16 + g + rh * 8;
                int co_g = co_base + co_t;
                float d   = dm[b * C_ + co_g];
                float bb  = Bvec[co_g];
                float s2v = g_s2[b * C_ + co_g];
                #pragma unroll
                for (int f = 0; f < 6; f++) {
                    #pragma unroll
                    for (int rl = 0; rl < 2; rl++) {
                        int col = wn * 48 + f * 8 + c2 + rl;
                        int p = P0 + col;
                        int y = p / QW;
                        int x = p - y * QW;
                        float v = 0.f;
                        if (x < 64 && y < 64) {
                            v = d * acc[mi][f][rh * 2 + rl] + bb * noise[b * PIX + y * 64 + x];
                            v = (v >= 0.f) ? v : SLOPE * v;
                            v *= s2v;
                        }
                        *(__half*)(dsm + col * RS + co_t * 2) = __float2half_rn(v);
                    }
                }
            }
        }
        __syncthreads();
        for (int i = tid; i < NT * 16; i += 256) {
            int px = i >> 4, j = i & 15;
            int p = P0 + px;
            int y = p / QW;
            int x = p - y * QW;
            if (x < 64 && y < 64) {
                uint4 val = *(const uint4*)(dsm + px * RS + j * 16);
                char* dst = (char*)(g_x2 + ((size_t)b * SLAB + (y + 1) * QW + (x + 1)) * C_ + co_base);
                *(uint4*)(dst + j * 16) = val;
            }
        }
    } else {
        #pragma unroll
        for (int mi = 0; mi < 4; mi++) {
            #pragma unroll
            for (int rh = 0; rh < 2; rh++) {
                int co_g = co_base + wm * 64 + mi * 16 + g + rh * 8;
                float d  = dm[b * C_ + co_g];
                float bb = Bvec[co_g];
                #pragma unroll
                for (int f = 0; f < 6; f++) {
                    #pragma unroll
                    for (int rl = 0; rl < 2; rl++) {
                        int col = wn * 48 + f * 8 + c2 + rl;
                        int p = P0 + col;
                        int y = p / QW;
                        int x = p - y * QW;
                        if (x < 64 && y < 64) {
                            float v = d * acc[mi][f][rh * 2 + rl] + bb * noise[b * PIX + y * 64 + x];
                            v = (v >= 0.f) ? v : SLOPE * v;
                            outx[((size_t)(b * C_ + co_g)) * PIX + y * 64 + x] = v;
                        }
                    }
                }
            }
        }
    }
}

// ---------------- toRGB 1x1 + rgb upsample + add ----------------------------
__device__ __forceinline__ float bilerp32(const float* __restrict__ p, int y, int x)
{
    const float F = 31.0f / 63.0f;
    float cy = (float)y * F, cx = (float)x * F;
    int iy0 = (int)cy, ix0 = (int)cx;
    float ty = cy - (float)iy0, tx = cx - (float)ix0;
    int iy1 = min(iy0 + 1, 31), ix1 = min(ix0 + 1, 31);
    float v00 = p[iy0 * 32 + ix0], v01 = p[iy0 * 32 + ix1];
    float v10 = p[iy1 * 32 + ix0], v11 = p[iy1 * 32 + ix1];
    float a = v00 * (1.f - ty) + v10 * ty;
    float c = v01 * (1.f - ty) + v11 * ty;
    return a * (1.f - tx) + c * tx;
}

__global__ void k_final(const float* __restrict__ y2,
                        const float* __restrict__ rgb_in,
                        const float* __restrict__ noise3,
                        const float* __restrict__ B3,
                        float* __restrict__ out_rgb)
{
    int b = blockIdx.y;
    int p = blockIdx.x * 256 + threadIdx.x;
    __shared__ float s_m3[3 * C_];
    for (int i = threadIdx.x; i < 3 * C_; i += 256) s_m3[i] = g_m3[b * 3 * C_ + i];
    __syncthreads();

    int y = p >> 6, x = p & 63;
    const float* yb = y2 + (size_t)b * C_ * PIX + p;
    float a0 = 0.f, a1 = 0.f, a2 = 0.f;
    #pragma unroll 8
    for (int ci = 0; ci < C_; ci++) {
        float v = yb[(size_t)ci * PIX];
        a0 = fmaf(s_m3[ci], v, a0);
        a1 = fmaf(s_m3[C_ + ci], v, a1);
        a2 = fmaf(s_m3[2 * C_ + ci], v, a2);
    }
    float nz = noise3[b * PIX + p];
    float a[3] = {a0, a1, a2};
    #pragma unroll
    for (int j = 0; j < 3; j++) {
        float v = a[j] + B3[j] * nz;
        v = (v >= 0.f) ? v : SLOPE * v;
        const float* rp = rgb_in + (size_t)(b * 3 + j) * 1024;
        out_rgb[(size_t)(b * 3 + j) * PIX + p] = bilerp32(rp, y, x) + v;
    }
}

// ---------------- launcher ---------------------------------------------------
extern "C" void kernel_launch(void* const* d_in, const int* in_sizes, int n_in,
                              void* d_out, int out_size)
{
    const float* x    = (const float*)d_in[0];
    const float* rgb  = (const float*)d_in[1];
    const float* w    = (const float*)d_in[2];
    const float* n1   = (const float*)d_in[3];
    const float* n2   = (const float*)d_in[4];
    const float* n3   = (const float*)d_in[5];
    const float* wt1  = (const float*)d_in[6];
    const float* A1w  = (const float*)d_in[7];
    const float* A1b  = (const float*)d_in[8];
    const float* B1   = (const float*)d_in[9];
    const float* wt2  = (const float*)d_in[10];
    const float* A2w  = (const float*)d_in[11];
    const float* A2b  = (const float*)d_in[12];
    const float* B2   = (const float*)d_in[13];
    const float* wt3  = (const float*)d_in[14];
    const float* A3w  = (const float*)d_in[15];
    const float* A3b  = (const float*)d_in[16];
    const float* B3   = (const float*)d_in[17];
    float* out = (float*)d_out;

    cudaFuncSetAttribute(k_conv, cudaFuncAttributeMaxDynamicSharedMemorySize, SMEM_CONV);

    k_prep  <<<3584, 256>>>(w, A1w, A1b, A2w, A2b, A3w, A3b, wt1, wt2);
    k_demod <<<(2 * B_ * C_ + 7) / 8, 256>>>();
    k_m3    <<<B_ * 3, 128>>>(wt3);
    k_zero  <<<B_ * 400, 256>>>();
    k_up    <<<dim3(64, 8, B_), 256>>>(x);
    k_conv  <<<dim3(NTILES, 4, B_), 256, SMEM_CONV>>>(0, n1, B1, out);
    k_conv  <<<dim3(NTILES, 4, B_), 256, SMEM_CONV>>>(1, n2, B2, out);
    k_final <<<dim3(PIX / 256, B_), 256>>>(out, rgb, n3, B3, out + (size_t)XEL);
}

// round 16
// speedup vs baseline: 1.1859x; 1.1333x over previous
#include <cuda_runtime.h>
#include <cuda_fp16.h>
#include <cstdint>

// ============================================================================
// BlockG via mma.sync fp16 single-term implicit GEMM.
//   conv = scale-input-by-style, shared-weight conv, scale-output-by-demod.
//   3x3 conv = 9 row-offset taps into one padded-NHWC smem region.
//   3-taps-per-stage weight pipeline (3 x 48KB buffers, wait_group 1):
//   24 sync points instead of 72; X restage never blocks on just-issued W.
//   192-px n-tiles: 4224 = 22*192 exactly -> no junk tile, 704 CTAs.
// Output: d_out[0:8*512*64*64) = x (fp32 NCHW), then [..:+8*3*64*64) = rgb.
// ============================================================================

#define B_ 8
#define C_ 512
#define PIX 4096
#define XEL (B_*C_*PIX)
#define QW 66
#define SLAB 4496
#define NT 192
#define NTILES 22
#define REGROWS 326
#define NSTAGE 24              // 8 chunks * 3 stages (3 taps each)
#define EPSV 1e-8f
#define SLOPE 0.2f

// dynamic smem layout (bytes)
#define OFF_X  0
#define OFF_W  41728           // 326*128
#define WBUF3  49152           // 3 taps * 16384
#define SMEM_CONV 189184       // 41728 + 3*49152

// ---------------- device scratch ----------------
__device__ __half g_x1[B_*SLAB*C_];                 // conv1 input (padded NHWC fp16)
__device__ __half g_x2[B_*SLAB*C_];                 // conv2 input
__device__ __half g_wb1[9*C_*C_], g_wb2[9*C_*C_];   // [tap][co][ci] fp16
__device__ float g_w2s1[C_*C_], g_w2s2[C_*C_];
__device__ float g_s1[B_*C_], g_s2[B_*C_], g_s3[B_*C_];
__device__ float g_d1[B_*C_], g_d2[B_*C_];
__device__ float g_m3[B_*3*C_];

// ---------------- helpers ----------------
__device__ __forceinline__ uint32_t smem_u32(const void* p) {
    uint32_t a;
    asm("{ .reg .u64 t; cvta.to.shared.u64 t, %1; cvt.u32.u64 %0, t; }" : "=r"(a) : "l"(p));
    return a;
}
__device__ __forceinline__ uint32_t swz(uint32_t o) { return o ^ ((o >> 3) & 0x70); }

__device__ __forceinline__ void cpa16(uint32_t dst, const void* gsrc) {
    asm volatile("cp.async.cg.shared.global [%0], [%1], 16;"
        :: "r"(dst), "l"(__cvta_generic_to_global(gsrc)) : "memory");
}
__device__ __forceinline__ void cpa_commit() {
    asm volatile("cp.async.commit_group;" ::: "memory");
}
__device__ __forceinline__ void cpa_wait0() {
    asm volatile("cp.async.wait_group 0;" ::: "memory");
}
__device__ __forceinline__ void cpa_wait1() {
    asm volatile("cp.async.wait_group 1;" ::: "memory");
}

__device__ __forceinline__ void ldsm4(uint32_t* r, uint32_t addr) {
    asm volatile("ldmatrix.sync.aligned.m8n8.x4.shared.b16 {%0,%1,%2,%3}, [%4];"
        : "=r"(r[0]), "=r"(r[1]), "=r"(r[2]), "=r"(r[3]) : "r"(addr));
}
__device__ __forceinline__ void mma16816(float* c, const uint32_t* a, uint32_t b0, uint32_t b1) {
    asm volatile("mma.sync.aligned.m16n8k16.row.col.f32.f16.f16.f32 "
        "{%0,%1,%2,%3}, {%4,%5,%6,%7}, {%8,%9}, {%0,%1,%2,%3};"
        : "+f"(c[0]), "+f"(c[1]), "+f"(c[2]), "+f"(c[3])
        : "r"(a[0]), "r"(a[1]), "r"(a[2]), "r"(a[3]), "r"(b0), "r"(b1));
}

// ---------------- styles + weight prep + border zero (merged) ---------------
// blocks [0,1536): styles; [1536,3584): wprep; [3584,6784): border zero
__global__ void k_prep(const float* __restrict__ w,
                       const float* __restrict__ A1, const float* __restrict__ b1,
                       const float* __restrict__ A2, const float* __restrict__ b2,
                       const float* __restrict__ A3, const float* __restrict__ b3,
                       const float* __restrict__ w1, const float* __restrict__ w2)
{
    if (blockIdx.x < 1536) {
        int gw = (blockIdx.x * 256 + threadIdx.x) >> 5;
        int lane = threadIdx.x & 31;
        int m = gw / (B_ * C_);
        int r = gw - m * (B_ * C_);
        int b = r >> 9, i = r & 511;
        const float* A  = (m == 0) ? A1 : (m == 1) ? A2 : A3;
        const float* bs = (m == 0) ? b1 : (m == 1) ? b2 : b3;
        float acc = 0.f;
        const float* wb = w + b * C_;
        const float* Ai = A + i * C_;
        for (int k = lane; k < C_; k += 32) acc += wb[k] * Ai[k];
        #pragma unroll
        for (int o = 16; o > 0; o >>= 1) acc += __shfl_xor_sync(0xffffffffu, acc, o);
        if (lane == 0) {
            float* out = (m == 0) ? g_s1 : (m == 1) ? g_s2 : g_s3;
            out[b * C_ + i] = acc + bs[i];
        }
    } else if (blockIdx.x < 3584) {
        int idx = (blockIdx.x - 1536) * 256 + threadIdx.x;
        int m = idx >> 18;
        int r = idx & (C_ * C_ - 1);
        int co = r >> 9, ci = r & 511;
        const float* wsrc = m ? w2 : w1;
        float* w2s = m ? g_w2s2 : g_w2s1;
        __half* wh = m ? g_wb2 : g_wb1;
        const float* src = wsrc + (size_t)(co * C_ + ci) * 9;
        float ss = 0.f;
        #pragma unroll
        for (int t = 0; t < 9; t++) {
            float v = src[t];
            ss += v * v;
            wh[((size_t)t * C_ + co) * C_ + ci] = __float2half_rn(v);
        }
        w2s[co * C_ + ci] = ss;
    } else {
        int r = blockIdx.x - 3584;
        int i = r % 400;
        int b = r / 400;
        int q;
        if (i < 66)       q = i;                          // top row
        else if (i < 132) q = 4290 + (i - 66);            // bottom row
        else if (i < 196) q = (i - 132 + 1) * QW;         // left col
        else if (i < 260) q = (i - 196 + 1) * QW + 65;    // right col
        else              q = 4356 + (i - 260);           // tail rows
        size_t o = ((size_t)b * SLAB + q) * C_ / 2 + threadIdx.x;
        ((uint32_t*)g_x1)[o] = 0u;
        ((uint32_t*)g_x2)[o] = 0u;
    }
}

// ---------------- demod + toRGB modulation (merged) -------------------------
// blocks [0,1024): demod; [1024,1048): m3
__global__ void k_dm(const float* __restrict__ w3)
{
    if (blockIdx.x < 1024) {
        int gw = (blockIdx.x * 256 + threadIdx.x) >> 5;
        int lane = threadIdx.x & 31;
        int m = gw >> 12;
        int r = gw & 4095;
        int b = r >> 9, co = r & 511;
        const float* w2s = m ? g_w2s2 : g_w2s1;
        const float* s   = m ? g_s2   : g_s1;
        float acc = 0.f;
        const float* wr = w2s + co * C_;
        const float* sr = s + b * C_;
        for (int ci = lane; ci < C_; ci += 32) { float sv = sr[ci]; acc += wr[ci] * sv * sv; }
        #pragma unroll
        for (int o = 16; o > 0; o >>= 1) acc += __shfl_xor_sync(0xffffffffu, acc, o);
        if (lane == 0) {
            float* d = m ? g_d2 : g_d1;
            d[b * C_ + co] = rsqrtf(acc + EPSV);
        }
    } else {
        int r = blockIdx.x - 1024;
        int b = r / 3, j = r % 3;
        __shared__ float red[256];
        __shared__ float d3s;
        int tid = threadIdx.x;
        float acc = 0.f;
        for (int ci = tid; ci < C_; ci += 256) {
            float t = w3[j * C_ + ci] * g_s3[b * C_ + ci];
            acc += t * t;
        }
        red[tid] = acc; __syncthreads();
        for (int o = 128; o > 0; o >>= 1) { if (tid < o) red[tid] += red[tid + o]; __syncthreads(); }
        if (tid == 0) d3s = rsqrtf(red[0] + EPSV);
        __syncthreads();
        float d3 = d3s;
        for (int ci = tid; ci < C_; ci += 256)
            g_m3[(b * 3 + j) * C_ + ci] = w3[j * C_ + ci] * g_s3[b * C_ + ci] * d3;
    }
}

// ---------------- upsample x2 + style, write fp16 NHWC ----------------------
__global__ void k_up(const float* __restrict__ xin)
{
    int y = blockIdx.x, cc = blockIdx.y, b = blockIdx.z;
    int ci0 = cc * 64;
    __shared__ float sin_[2][64][33];
    __shared__ float ss1[64];
    const float F = 31.0f / 63.0f;
    float cy = (float)y * F;
    int iy0 = (int)cy;
    float ty = cy - (float)iy0;
    int iy1 = min(iy0 + 1, 31);
    int tid = threadIdx.x;
    for (int i = tid; i < 2 * 64 * 32; i += 256) {
        int rr = i >> 11, rem = i & 2047, c = rem >> 5, xx = rem & 31;
        int iy = rr ? iy1 : iy0;
        sin_[rr][c][xx] = xin[((size_t)(b * C_ + ci0 + c) * 32 + iy) * 32 + xx];
    }
    if (tid < 64) ss1[tid] = g_s1[b * C_ + ci0 + tid];
    __syncthreads();
    #pragma unroll
    for (int j = 0; j < 16; j++) {
        int x = (tid >> 6) + j * 4;
        int c = tid & 63;
        float cx = (float)x * F;
        int ix0 = (int)cx;
        float tx = cx - (float)ix0;
        int ix1 = min(ix0 + 1, 31);
        float a0 = sin_[0][c][ix0] * (1.f - ty) + sin_[1][c][ix0] * ty;
        float a1 = sin_[0][c][ix1] * (1.f - ty) + sin_[1][c][ix1] * ty;
        float v = (a0 * (1.f - tx) + a1 * tx) * ss1[c];
        size_t o = ((size_t)b * SLAB + (y + 1) * QW + (x + 1)) * C_ + ci0 + c;
        g_x1[o] = __float2half_rn(v);
    }
}

// ---------------- mma.sync conv 3x3, 3-tap pipeline stages ------------------
// CTA: 128 co x 192 px, 8 warps (2m x 4n) each m64 x n48. Single fp16 term.
__global__ void __launch_bounds__(256)
k_conv(int pass, const float* __restrict__ noise, const float* __restrict__ Bvec,
       float* __restrict__ outx)
{
    extern __shared__ __align__(1024) char dsm[];

    const __half* xin = pass ? g_x2  : g_x1;
    const __half* wb  = pass ? g_wb2 : g_wb1;
    const float* dm = pass ? g_d2 : g_d1;

    int tid = threadIdx.x;
    int wid = tid >> 5, lane = tid & 31;
    int wm = wid & 1, wn = wid >> 1;          // warp pos: m (co), n (px 0..3)
    int b = blockIdx.z, cb = blockIdx.y, ntile = blockIdx.x;
    int P0 = ntile * NT;
    int co_base = cb * 128;

    uint32_t sb = smem_u32(dsm);
    uint32_t sX = sb + OFF_X;

    // ldmatrix lane geometry
    int a_row = ((lane >> 3) & 1) * 8 + (lane & 7);
    int a_kb  = (lane >> 4) * 16;
    int b_n   = (lane >> 4) * 8 + (lane & 7);
    int b_kb  = ((lane >> 3) & 1) * 16;

    float acc[4][6][4];
    #pragma unroll
    for (int mi = 0; mi < 4; mi++)
        #pragma unroll
        for (int f = 0; f < 6; f++)
            #pragma unroll
            for (int r = 0; r < 4; r++) acc[mi][f][r] = 0.f;

    uint32_t rowA[4];
    #pragma unroll
    for (int mi = 0; mi < 4; mi++)
        rowA[mi] = (uint32_t)((wm * 64 + mi * 16 + a_row) * 128 + a_kb);

    const size_t xgbase = ((size_t)b * SLAB + P0) * C_;

    auto stage_X = [&](int c) {
        int ci0 = c * 64;
        for (int i = tid; i < REGROWS * 8; i += 256) {
            int r = i >> 3, j = i & 7;
            size_t g = xgbase + (size_t)r * C_ + ci0 + j * 8;
            cpa16(sX + swz((uint32_t)(r * 128 + j * 16)), xin + g);
        }
    };
    // 3-tap weight tile for stage s into buffer s%3
    auto stage_W3 = [&](int s) {
        int c = s / 3, sub = s - c * 3;
        int ci0 = c * 64;
        uint32_t base = sb + OFF_W + (uint32_t)(s % 3) * WBUF3;
        #pragma unroll
        for (int t = 0; t < 3; t++) {
            int tap = sub * 3 + t;
            const size_t wgbase = ((size_t)(tap * C_ + co_base)) * C_ + ci0;
            uint32_t tb = base + t * 16384;
            for (int i = tid; i < 128 * 8; i += 256) {
                int r = i >> 3, j = i & 7;
                cpa16(tb + swz((uint32_t)(r * 128 + j * 16)),
                      wb + wgbase + (size_t)r * C_ + j * 8);
            }
        }
    };

    // prologue: X(0)+W3(0) as group0, W3(1) as group1; drain group0; publish.
    stage_X(0);
    stage_W3(0);
    cpa_commit();
    stage_W3(1);
    cpa_commit();
    cpa_wait1();                // X + W3(0) landed
    __syncthreads();

    for (int s = 0; s < NSTAGE; s++) {
        int c = s / 3, sub = s - c * 3;
        bool xmove = (sub == 0 && c > 0);

        if (s > 0) __syncthreads();    // readers of buf (s+2)%3 and X done
        if (xmove) {                   // X as its OWN group (older than W)
            stage_X(c);
            cpa_commit();
        }
        if (s + 2 < NSTAGE) stage_W3(s + 2);
        cpa_commit();
        cpa_wait1();                   // drains X (if xmove) / W3(s+1); leaves newest
        if (xmove) __syncthreads();    // publish freshly staged X

        uint32_t wbase = sb + OFF_W + (uint32_t)(s % 3) * WBUF3;
        #pragma unroll
        for (int t = 0; t < 3; t++) {
            int tap = sub * 3 + t;
            uint32_t sW = wbase + t * 16384;
            int toff = (tap / 3) * QW + (tap % 3);
            uint32_t rowB[3];
            #pragma unroll
            for (int nj = 0; nj < 3; nj++)
                rowB[nj] = (uint32_t)((wn * 48 + nj * 16 + b_n + toff) * 128 + b_kb);

            #pragma unroll
            for (int ks = 0; ks < 4; ks++) {
                uint32_t kadd = ks * 32;
                uint32_t Aw[4][4], Bx[3][4];
                #pragma unroll
                for (int mi = 0; mi < 4; mi++)
                    ldsm4(Aw[mi], sW + swz(rowA[mi] + kadd));
                #pragma unroll
                for (int nj = 0; nj < 3; nj++)
                    ldsm4(Bx[nj], sX + swz(rowB[nj] + kadd));
                #pragma unroll
                for (int mi = 0; mi < 4; mi++) {
                    #pragma unroll
                    for (int f = 0; f < 6; f++) {
                        int bi = f >> 1, br = (f & 1) * 2;
                        mma16816(acc[mi][f], Aw[mi], Bx[bi][br], Bx[bi][br + 1]);
                    }
                }
            }
        }
    }

    // ---------------- epilogue ----------------
    int g = lane >> 2, c2 = (lane & 3) * 2;
    if (pass == 0) {
        // stage [col][co] fp16 in smem (row stride 272B), then coalesced store
        __syncthreads();               // mainloop smem reads done
        const int RS = 272;
        #pragma unroll
        for (int mi = 0; mi < 4; mi++) {
            #pragma unroll
            for (int rh = 0; rh < 2; rh++) {
                int co_t = wm * 64 + mi * 16 + g + rh * 8;
                int co_g = co_base + co_t;
                float d   = dm[b * C_ + co_g];
                float bb  = Bvec[co_g];
                float s2v = g_s2[b * C_ + co_g];
                #pragma unroll
                for (int f = 0; f < 6; f++) {
                    #pragma unroll
                    for (int rl = 0; rl < 2; rl++) {
                        int col = wn * 48 + f * 8 + c2 + rl;
                        int p = P0 + col;
                        int y = p / QW;
                        int x = p - y * QW;
                        float v = 0.f;
                        if (x < 64 && y < 64) {
                            v = d * acc[mi][f][rh * 2 + rl] + bb * noise[b * PIX + y * 64 + x];
                            v = (v >= 0.f) ? v : SLOPE * v;
                            v *= s2v;
                        }
                        *(__half*)(dsm + col * RS + co_t * 2) = __float2half_rn(v);
                    }
                }
            }
        }
        __syncthreads();
        for (int i = tid; i < NT * 16; i += 256) {
            int px = i >> 4, j = i & 15;
            int p = P0 + px;
            int y = p / QW;
            int x = p - y * QW;
            if (x < 64 && y < 64) {
                uint4 val = *(const uint4*)(dsm + px * RS + j * 16);
                char* dst = (char*)(g_x2 + ((size_t)b * SLAB + (y + 1) * QW + (x + 1)) * C_ + co_base);
                *(uint4*)(dst + j * 16) = val;
            }
        }
    } else {
        #pragma unroll
        for (int mi = 0; mi < 4; mi++) {
            #pragma unroll
            for (int rh = 0; rh < 2; rh++) {
                int co_g = co_base + wm * 64 + mi * 16 + g + rh * 8;
                float d  = dm[b * C_ + co_g];
                float bb = Bvec[co_g];
                #pragma unroll
                for (int f = 0; f < 6; f++) {
                    #pragma unroll
                    for (int rl = 0; rl < 2; rl++) {
                        int col = wn * 48 + f * 8 + c2 + rl;
                        int p = P0 + col;
                        int y = p / QW;
                        int x = p - y * QW;
                        if (x < 64 && y < 64) {
                            float v = d * acc[mi][f][rh * 2 + rl] + bb * noise[b * PIX + y * 64 + x];
                            v = (v >= 0.f) ? v : SLOPE * v;
                            outx[((size_t)(b * C_ + co_g)) * PIX + y * 64 + x] = v;
                        }
                    }
                }
            }
        }
    }
}

// ---------------- toRGB 1x1 + rgb upsample + add ----------------------------
__device__ __forceinline__ float bilerp32(const float* __restrict__ p, int y, int x)
{
    const float F = 31.0f / 63.0f;
    float cy = (float)y * F, cx = (float)x * F;
    int iy0 = (int)cy, ix0 = (int)cx;
    float ty = cy - (float)iy0, tx = cx - (float)ix0;
    int iy1 = min(iy0 + 1, 31), ix1 = min(ix0 + 1, 31);
    float v00 = p[iy0 * 32 + ix0], v01 = p[iy0 * 32 + ix1];
    float v10 = p[iy1 * 32 + ix0], v11 = p[iy1 * 32 + ix1];
    float a = v00 * (1.f - ty) + v10 * ty;
    float c = v01 * (1.f - ty) + v11 * ty;
    return a * (1.f - tx) + c * tx;
}

__global__ void k_final(const float* __restrict__ y2,
                        const float* __restrict__ rgb_in,
                        const float* __restrict__ noise3,
                        const float* __restrict__ B3,
                        float* __restrict__ out_rgb)
{
    int b = blockIdx.y;
    int p = blockIdx.x * 256 + threadIdx.x;
    __shared__ float s_m3[3 * C_];
    for (int i = threadIdx.x; i < 3 * C_; i += 256) s_m3[i] = g_m3[b * 3 * C_ + i];
    __syncthreads();

    int y = p >> 6, x = p & 63;
    const float* yb = y2 + (size_t)b * C_ * PIX + p;
    float a0 = 0.f, a1 = 0.f, a2 = 0.f;
    #pragma unroll 8
    for (int ci = 0; ci < C_; ci++) {
        float v = yb[(size_t)ci * PIX];
        a0 = fmaf(s_m3[ci], v, a0);
        a1 = fmaf(s_m3[C_ + ci], v, a1);
        a2 = fmaf(s_m3[2 * C_ + ci], v, a2);
    }
    float nz = noise3[b * PIX + p];
    float a[3] = {a0, a1, a2};
    #pragma unroll
    for (int j = 0; j < 3; j++) {
        float v = a[j] + B3[j] * nz;
        v = (v >= 0.f) ? v : SLOPE * v;
        const float* rp = rgb_in + (size_t)(b * 3 + j) * 1024;
        out_rgb[(size_t)(b * 3 + j) * PIX + p] = bilerp32(rp, y, x) + v;
    }
}

// ---------------- launcher ---------------------------------------------------
extern "C" void kernel_launch(void* const* d_in, const int* in_sizes, int n_in,
                              void* d_out, int out_size)
{
    const float* x    = (const float*)d_in[0];
    const float* rgb  = (const float*)d_in[1];
    const float* w    = (const float*)d_in[2];
    const float* n1   = (const float*)d_in[3];
    const float* n2   = (const float*)d_in[4];
    const float* n3   = (const float*)d_in[5];
    const float* wt1  = (const float*)d_in[6];
    const float* A1w  = (const float*)d_in[7];
    const float* A1b  = (const float*)d_in[8];
    const float* B1   = (const float*)d_in[9];
    const float* wt2  = (const float*)d_in[10];
    const float* A2w  = (const float*)d_in[11];
    const float* A2b  = (const float*)d_in[12];
    const float* B2   = (const float*)d_in[13];
    const float* wt3  = (const float*)d_in[14];
    const float* A3w  = (const float*)d_in[15];
    const float* A3b  = (const float*)d_in[16];
    const float* B3   = (const float*)d_in[17];
    float* out = (float*)d_out;

    cudaFuncSetAttribute(k_conv, cudaFuncAttributeMaxDynamicSharedMemorySize, SMEM_CONV);

    k_prep  <<<6784, 256>>>(w, A1w, A1b, A2w, A2b, A3w, A3b, wt1, wt2);
    k_dm    <<<1048, 256>>>(wt3);
    k_up    <<<dim3(64, 8, B_), 256>>>(x);
    k_conv  <<<dim3(NTILES, 4, B_), 256, SMEM_CONV>>>(0, n1, B1, out);
    k_conv  <<<dim3(NTILES, 4, B_), 256, SMEM_CONV>>>(1, n2, B2, out);
    k_final <<<dim3(PIX / 256, B_), 256>>>(out, rgb, n3, B3, out + (size_t)XEL);
}